// round 7
// baseline (speedup 1.0000x reference)
#include <cuda_runtime.h>
#include <math.h>

#ifndef M_PI
#define M_PI 3.14159265358979323846
#endif

#define NIMG 124
#define NSIDE 128
#define NPIX (NSIDE*NSIDE)
#define NTOT (NIMG*NPIX)
#define LAM_C 0.1f
#define SPAD 132                    // smem row stride in floats (16B-aligned rows, 4-bank skew)
#define NTHR 1024

typedef unsigned long long ull;

// ---- persistent state (no cudaMalloc allowed) ----
__device__ float g_X[NTOT], g_G1[NTOT], g_G21[NTOT], g_G22[NTOT];
__device__ float g_DhZ[NTOT], g_DvZ[NTOT];
__device__ float g_Q[NPIX];      // real orthogonal trig eigenbasis, row-major
__device__ float g_Qt[NPIX];     // its transpose
__device__ float g_lam[NSIDE];   // eigenvalues of 1D circular Laplacian

// ======================= init: Q, Q^T, eigenvalues =======================
__global__ void init_q_kernel() {
    int r = blockIdx.x, n = threadIdx.x;
    double inv = 1.0 / 128.0;
    double s1 = sqrt(inv), s2 = sqrt(2.0 * inv);
    float v;
    if (r == 0)        v = (float)s1;
    else if (r < 64)   v = (float)(s2 * cos(2.0 * M_PI * (double)r * (double)n * inv));
    else if (r == 64)  v = (n & 1) ? (float)(-s1) : (float)s1;
    else               v = (float)(s2 * sin(2.0 * M_PI * (double)(r - 64) * (double)n * inv));
    g_Q[r * NSIDE + n]  = v;
    g_Qt[n * NSIDE + r] = v;
    if (n == 0) {
        int f = (r <= 64) ? r : (r - 64);
        g_lam[r] = (float)(2.0 - 2.0 * cos(2.0 * M_PI * (double)f * inv));
    }
}

__device__ __forceinline__ float shrinkf(float x, float t) {
    return copysignf(fmaxf(fabsf(x) - t, 0.f), x);
}

// packed fp32x2 helpers (Blackwell FFMA2)
__device__ __forceinline__ ull pack2(float x) {
    ull r; asm("mov.b64 %0, {%1, %1};" : "=l"(r) : "f"(x)); return r;
}
__device__ __forceinline__ void ffma2(ull& d, ull a, ull b) {
    asm("fma.rn.f32x2 %0, %1, %2, %0;" : "+l"(d) : "l"(a), "l"(b));
}

__device__ __forceinline__ float4 ld4(const float* p) { return *(const float4*)p; }
__device__ __forceinline__ void st4(float* p, float4 v) { *(float4*)p = v; }

// ============ one 128x128x128 GEMM stage in shared memory; C may alias L or R ============
// C[m][n] = sum_k L[m][k] * R[k][n]   (optionally * spectral filter)
// 1024 threads = 32 warps; warp w owns rows [16*(w>>2), +16), cols [32*(w&3), +32);
// lane owns rows row0..row0+3 (row0 = wrow + 4*(lane>>3)), cols col0..col0+3 (col0 = wcol + 4*(lane&7)).
template<bool FILT>
__device__ __forceinline__ void gemm_stage(const float* __restrict__ Lb,
                                           const float* __restrict__ Rb,
                                           float* __restrict__ Cb,
                                           const float* __restrict__ lam,
                                           float mu1, float mu2, int row0, int col0) {
    ull acc[4][2];
#pragma unroll
    for (int i = 0; i < 4; i++) { acc[i][0] = 0ull; acc[i][1] = 0ull; }

    const float* lrow = Lb + row0 * SPAD;
    const float* rcol = Rb + col0;

#pragma unroll 2
    for (int k0 = 0; k0 < 128; k0 += 4) {
        float4 A[4];
#pragma unroll
        for (int i = 0; i < 4; i++) A[i] = ld4(lrow + i * SPAD + k0);
#pragma unroll
        for (int kk = 0; kk < 4; kk++) {
            ulonglong2 b = *(const ulonglong2*)(rcol + (k0 + kk) * SPAD);
#pragma unroll
            for (int i = 0; i < 4; i++) {
                float av = (kk == 0) ? A[i].x : (kk == 1) ? A[i].y : (kk == 2) ? A[i].z : A[i].w;
                ull aa = pack2(av);
                ffma2(acc[i][0], aa, b.x);
                ffma2(acc[i][1], aa, b.y);
            }
        }
    }
    __syncthreads();   // all reads of the (possibly aliased) buffer complete before any write

    float lc0, lc1, lc2, lc3;
    if (FILT) { lc0 = lam[col0]; lc1 = lam[col0 + 1]; lc2 = lam[col0 + 2]; lc3 = lam[col0 + 3]; }
#pragma unroll
    for (int i = 0; i < 4; i++) {
        int r = row0 + i;
        float2 v0 = *reinterpret_cast<float2*>(&acc[i][0]);
        float2 v1 = *reinterpret_cast<float2*>(&acc[i][1]);
        float4 v = make_float4(v0.x, v0.y, v1.x, v1.y);
        if (FILT) {
            float lr = lam[r];
            v.x *= 1.f / (mu1 + mu2 * (lr + lc0));
            v.y *= 1.f / (mu1 + mu2 * (lr + lc1));
            v.z *= 1.f / (mu1 + mu2 * (lr + lc2));
            v.w *= 1.f / (mu1 + mu2 * (lr + lc3));
        }
        st4(&Cb[r * SPAD + col0], v);
    }
    __syncthreads();   // stores visible before next stage reads
}

// ======================= fused whole-problem kernel: 1 CTA per image =======================
extern __shared__ float smem[];

__global__ void __launch_bounds__(NTHR, 1)
hwtv_fused(const float* __restrict__ Y, const float* __restrict__ inW,
           float* __restrict__ out) {
    float* sQ   = smem;
    float* sQt  = smem + 128 * SPAD;
    float* sT   = smem + 2 * 128 * SPAD;
    float* sLam = smem + 3 * 128 * SPAD;

    int tid = threadIdx.x;
    int w = tid >> 5, lane = tid & 31;
    int row0 = (w >> 2) * 16 + (lane >> 3) * 4;
    int col0 = (w & 3) * 32 + (lane & 7) * 4;
    int base = blockIdx.x * NPIX;

    // stage Q / Q^T / lam into smem (padded layout)
    for (int p = tid; p < NPIX; p += NTHR) {
        int r = p >> 7, c = p & 127;
        sQ[r * SPAD + c]  = g_Q[p];
        sQt[r * SPAD + c] = g_Qt[p];
    }
    if (tid < 128) sLam[tid] = g_lam[tid];

    // init ADMM state for this image
    for (int p = tid; p < NPIX; p += NTHR) {
        int i = p >> 7, j = p & 127;
        int idx = base + p;
        float y = Y[idx];
        g_X[idx] = y;
        g_G1[idx] = 0.f; g_G21[idx] = 0.f; g_G22[idx] = 0.f;
        g_DhZ[idx] = y - Y[base + (i << 7) + ((j - 1) & 127)];
        g_DvZ[idx] = y - Y[base + (((i - 1) & 127) << 7) + j];
    }
    __syncthreads();

    double m1d = 0.1, m2d = 0.1;
    for (int t = 0; t < 20; t++) {
        float mu1 = (float)m1d, mu2 = (float)m2d;
        float inv2 = 1.f / mu2, thr = LAM_C * inv2;

        // ---- pre: shrink + build RHS directly into smem (4 px per step) ----
        // R = mu1*X + G1 + DhT(mu2*Uh+G21) + DvT(mu2*Uv+G22)
        for (int ch = tid; ch < NPIX / 4; ch += NTHR) {
            int i = ch >> 5, c0 = (ch & 31) * 4;
            int idx = base + (i << 7) + c0;

            float4 dh = ld4(&g_DhZ[idx]), dv = ld4(&g_DvZ[idx]);
            float4 g21 = ld4(&g_G21[idx]), g22 = ld4(&g_G22[idx]);
            float4 x4 = ld4(&g_X[idx]),  g1 = ld4(&g_G1[idx]);

            float4 Ph, Pv;
            Ph.x = mu2 * shrinkf(dh.x - g21.x * inv2, thr) + g21.x;
            Ph.y = mu2 * shrinkf(dh.y - g21.y * inv2, thr) + g21.y;
            Ph.z = mu2 * shrinkf(dh.z - g21.z * inv2, thr) + g21.z;
            Ph.w = mu2 * shrinkf(dh.w - g21.w * inv2, thr) + g21.w;
            Pv.x = mu2 * shrinkf(dv.x - g22.x * inv2, thr) + g22.x;
            Pv.y = mu2 * shrinkf(dv.y - g22.y * inv2, thr) + g22.y;
            Pv.z = mu2 * shrinkf(dv.z - g22.z * inv2, thr) + g22.z;
            Pv.w = mu2 * shrinkf(dv.w - g22.w * inv2, thr) + g22.w;

            int jr = (c0 + 4) & 127;
            int idr = base + (i << 7) + jr;
            float dh_r = g_DhZ[idr], g21_r = g_G21[idr];
            float Ph4 = mu2 * shrinkf(dh_r - g21_r * inv2, thr) + g21_r;

            int idd = base + (((i + 1) & 127) << 7) + c0;
            float4 dv_d = ld4(&g_DvZ[idd]), g22_d = ld4(&g_G22[idd]);
            float4 Pvd;
            Pvd.x = mu2 * shrinkf(dv_d.x - g22_d.x * inv2, thr) + g22_d.x;
            Pvd.y = mu2 * shrinkf(dv_d.y - g22_d.y * inv2, thr) + g22_d.y;
            Pvd.z = mu2 * shrinkf(dv_d.z - g22_d.z * inv2, thr) + g22_d.z;
            Pvd.w = mu2 * shrinkf(dv_d.w - g22_d.w * inv2, thr) + g22_d.w;

            float4 R;
            R.x = mu1 * x4.x + g1.x + (Ph.x - Ph.y) + (Pv.x - Pvd.x);
            R.y = mu1 * x4.y + g1.y + (Ph.y - Ph.z) + (Pv.y - Pvd.y);
            R.z = mu1 * x4.z + g1.z + (Ph.z - Ph.w) + (Pv.z - Pvd.z);
            R.w = mu1 * x4.w + g1.w + (Ph.w - Ph4)  + (Pv.w - Pvd.w);
            st4(&sT[i * SPAD + c0], R);
        }
        __syncthreads();

        // ---- spectral solve: Z = Q^T [ (Q R Q^T) ⊙ D ] Q, all in-place in sT ----
        gemm_stage<false>(sQ,  sT,  sT, sLam, mu1, mu2, row0, col0);   // T = Q * R
        gemm_stage<true >(sT,  sQt, sT, sLam, mu1, mu2, row0, col0);   // T = (T * Q^T) ⊙ D
        gemm_stage<false>(sQt, sT,  sT, sLam, mu1, mu2, row0, col0);   // T = Q^T * T
        gemm_stage<false>(sT,  sQ,  sT, sLam, mu1, mu2, row0, col0);   // T = T * Q  (= Z)

        if (t == 19) {
            for (int ch = tid; ch < NPIX / 4; ch += NTHR) {
                int i = ch >> 5, c0 = (ch & 31) * 4;
                st4(&out[base + (i << 7) + c0], ld4(&sT[i * SPAD + c0]));
            }
        } else {
            // ---- post: gradients of Z (smem) + X/G updates; Uh/Uv recomputed ----
            for (int ch = tid; ch < NPIX / 4; ch += NTHR) {
                int i = ch >> 5, c0 = (ch & 31) * 4;
                int idx = base + (i << 7) + c0;

                float4 z = ld4(&sT[i * SPAD + c0]);
                float zl = sT[i * SPAD + ((c0 - 1) & 127)];
                float4 zu = ld4(&sT[((i - 1) & 127) * SPAD + c0]);
                float4 dh, dv;
                dh.x = z.x - zl;  dh.y = z.y - z.x;  dh.z = z.z - z.y;  dh.w = z.w - z.z;
                dv.x = z.x - zu.x; dv.y = z.y - zu.y; dv.z = z.z - zu.z; dv.w = z.w - zu.w;

                float4 dho = ld4(&g_DhZ[idx]), dvo = ld4(&g_DvZ[idx]);
                float4 g21 = ld4(&g_G21[idx]), g22 = ld4(&g_G22[idx]);
                float4 g1 = ld4(&g_G1[idx]);
                float4 w4 = ld4(&inW[idx]), y = ld4(&Y[idx]);

                // recompute Uh/Uv from pre-iteration state (bit-identical to pre's values)
                float4 uh, uv;
                uh.x = shrinkf(dho.x - g21.x * inv2, thr); uh.y = shrinkf(dho.y - g21.y * inv2, thr);
                uh.z = shrinkf(dho.z - g21.z * inv2, thr); uh.w = shrinkf(dho.w - g21.w * inv2, thr);
                uv.x = shrinkf(dvo.x - g22.x * inv2, thr); uv.y = shrinkf(dvo.y - g22.y * inv2, thr);
                uv.z = shrinkf(dvo.z - g22.z * inv2, thr); uv.w = shrinkf(dvo.w - g22.w * inv2, thr);

                float4 x, g1n, g21n, g22n;
                x.x = (w4.x * y.x + mu1 * z.x - g1.x) / (w4.x + mu1);
                x.y = (w4.y * y.y + mu1 * z.y - g1.y) / (w4.y + mu1);
                x.z = (w4.z * y.z + mu1 * z.z - g1.z) / (w4.z + mu1);
                x.w = (w4.w * y.w + mu1 * z.w - g1.w) / (w4.w + mu1);
                g1n.x = g1.x + mu1 * (x.x - z.x); g1n.y = g1.y + mu1 * (x.y - z.y);
                g1n.z = g1.z + mu1 * (x.z - z.z); g1n.w = g1.w + mu1 * (x.w - z.w);
                g21n.x = g21.x + mu2 * (uh.x - dh.x); g21n.y = g21.y + mu2 * (uh.y - dh.y);
                g21n.z = g21.z + mu2 * (uh.z - dh.z); g21n.w = g21.w + mu2 * (uh.w - dh.w);
                g22n.x = g22.x + mu2 * (uv.x - dv.x); g22n.y = g22.y + mu2 * (uv.y - dv.y);
                g22n.z = g22.z + mu2 * (uv.z - dv.z); g22n.w = g22.w + mu2 * (uv.w - dv.w);

                st4(&g_DhZ[idx], dh); st4(&g_DvZ[idx], dv);
                st4(&g_X[idx], x);    st4(&g_G1[idx], g1n);
                st4(&g_G21[idx], g21n); st4(&g_G22[idx], g22n);
            }
            __syncthreads();
        }
        m1d *= 1.05; m2d *= 1.05;
    }
}

// ======================= launcher =======================
extern "C" void kernel_launch(void* const* d_in, const int* in_sizes, int n_in,
                              void* d_out, int out_size) {
    const float* Y   = (const float*)d_in[0];
    const float* inW = (const float*)d_in[1];
    float* out = (float*)d_out;

    const int smem_bytes = (3 * 128 * SPAD + 128) * (int)sizeof(float);  // 203,264 B
    cudaFuncSetAttribute(hwtv_fused, cudaFuncAttributeMaxDynamicSharedMemorySize, smem_bytes);

    init_q_kernel<<<128, 128>>>();
    hwtv_fused<<<NIMG, NTHR, smem_bytes>>>(Y, inW, out);
}

// round 8
// speedup vs baseline: 1.7816x; 1.7816x over previous
#include <cuda_runtime.h>
#include <math.h>

#ifndef M_PI
#define M_PI 3.14159265358979323846
#endif

#define NIMG 124
#define NSIDE 128
#define NPIX (NSIDE*NSIDE)
#define NTOT (NIMG*NPIX)
#define LAM_C 0.1f
#define SPAD 132                    // smem row stride in floats (16B-aligned rows; 132≡4 mod 32 banks)
#define NTHR 512

typedef unsigned long long ull;

// ---- persistent state (no cudaMalloc allowed) ----
__device__ float g_X[NTOT], g_G1[NTOT], g_G21[NTOT], g_G22[NTOT];
__device__ float g_DhZ[NTOT], g_DvZ[NTOT];
__device__ float g_Q[NPIX];      // real orthogonal trig eigenbasis, row-major
__device__ float g_Qt[NPIX];     // its transpose
__device__ float g_lam[NSIDE];   // eigenvalues of 1D circular Laplacian

// ======================= init: Q, Q^T, eigenvalues =======================
__global__ void init_q_kernel() {
    int r = blockIdx.x, n = threadIdx.x;
    double inv = 1.0 / 128.0;
    double s1 = sqrt(inv), s2 = sqrt(2.0 * inv);
    float v;
    if (r == 0)        v = (float)s1;
    else if (r < 64)   v = (float)(s2 * cos(2.0 * M_PI * (double)r * (double)n * inv));
    else if (r == 64)  v = (n & 1) ? (float)(-s1) : (float)s1;
    else               v = (float)(s2 * sin(2.0 * M_PI * (double)(r - 64) * (double)n * inv));
    g_Q[r * NSIDE + n]  = v;
    g_Qt[n * NSIDE + r] = v;
    if (n == 0) {
        int f = (r <= 64) ? r : (r - 64);
        g_lam[r] = (float)(2.0 - 2.0 * cos(2.0 * M_PI * (double)f * inv));
    }
}

__device__ __forceinline__ float shrinkf(float x, float t) {
    return copysignf(fmaxf(fabsf(x) - t, 0.f), x);
}

// packed fp32x2 helpers (Blackwell FFMA2)
__device__ __forceinline__ ull pack2(float x) {
    ull r; asm("mov.b64 %0, {%1, %1};" : "=l"(r) : "f"(x)); return r;
}
__device__ __forceinline__ void ffma2(ull& d, ull a, ull b) {
    asm("fma.rn.f32x2 %0, %1, %2, %0;" : "+l"(d) : "l"(a), "l"(b));
}

__device__ __forceinline__ float4 ld4(const float* p) { return *(const float4*)p; }
__device__ __forceinline__ void st4(float* p, float4 v) { *(float4*)p = v; }

// ============ one 128x128x128 GEMM stage in shared memory; C may alias L or R ============
// C[m][n] = sum_k L[m][k] * R[k][n]   (optionally * spectral filter)
// 512 threads = 16 warps in a 4x4 grid of 32x32 warp tiles.
// Lane micro-tile: rows row0 + 4*i (i<8), cols col0..col0+3.
//   row0 = (w>>2)*32 + (lane>>3)   -> row groups 1 apart => banks {0,4,8,12}, conflict-free
//   col0 = (w&3)*32 + (lane&7)*4   -> B reads: 128B consecutive, 4-way broadcast
template<bool FILT>
__device__ __forceinline__ void gemm_stage(const float* __restrict__ Lb,
                                           const float* __restrict__ Rb,
                                           float* __restrict__ Cb,
                                           const float* __restrict__ lam,
                                           float mu1, float mu2, int row0, int col0) {
    ull acc[8][2];
#pragma unroll
    for (int i = 0; i < 8; i++) { acc[i][0] = 0ull; acc[i][1] = 0ull; }

    const float* lrow = Lb + row0 * SPAD;
    const float* rcol = Rb + col0;

    ulonglong2 bcur = *(const ulonglong2*)(rcol);   // b for k=0
    for (int k0 = 0; k0 < 128; k0 += 4) {
        float4 A[8];
#pragma unroll
        for (int i = 0; i < 8; i++) A[i] = ld4(lrow + (i * 4) * SPAD + k0);
#pragma unroll
        for (int kk = 0; kk < 4; kk++) {
            ulonglong2 bnext = bcur;
            int kn = k0 + kk + 1;
            if (kn < 128) bnext = *(const ulonglong2*)(rcol + kn * SPAD);
#pragma unroll
            for (int i = 0; i < 8; i++) {
                float av = (kk == 0) ? A[i].x : (kk == 1) ? A[i].y : (kk == 2) ? A[i].z : A[i].w;
                ull aa = pack2(av);
                ffma2(acc[i][0], aa, bcur.x);
                ffma2(acc[i][1], aa, bcur.y);
            }
            bcur = bnext;
        }
    }
    __syncthreads();   // all reads of the (possibly aliased) buffer complete before any write

    float lc0, lc1, lc2, lc3;
    if (FILT) { lc0 = lam[col0]; lc1 = lam[col0 + 1]; lc2 = lam[col0 + 2]; lc3 = lam[col0 + 3]; }
#pragma unroll
    for (int i = 0; i < 8; i++) {
        int r = row0 + 4 * i;
        float2 v0 = *reinterpret_cast<float2*>(&acc[i][0]);
        float2 v1 = *reinterpret_cast<float2*>(&acc[i][1]);
        float4 v = make_float4(v0.x, v0.y, v1.x, v1.y);
        if (FILT) {
            float lr = lam[r];
            v.x *= 1.f / (mu1 + mu2 * (lr + lc0));
            v.y *= 1.f / (mu1 + mu2 * (lr + lc1));
            v.z *= 1.f / (mu1 + mu2 * (lr + lc2));
            v.w *= 1.f / (mu1 + mu2 * (lr + lc3));
        }
        st4(&Cb[r * SPAD + col0], v);
    }
    __syncthreads();   // stores visible before next stage reads
}

// ======================= fused whole-problem kernel: 1 CTA per image =======================
extern __shared__ float smem[];

__global__ void __launch_bounds__(NTHR, 1)
hwtv_fused(const float* __restrict__ Y, const float* __restrict__ inW,
           float* __restrict__ out) {
    float* sQ   = smem;
    float* sQt  = smem + 128 * SPAD;
    float* sT   = smem + 2 * 128 * SPAD;
    float* sLam = smem + 3 * 128 * SPAD;

    int tid = threadIdx.x;
    int w = tid >> 5, lane = tid & 31;
    int row0 = (w >> 2) * 32 + (lane >> 3);
    int col0 = (w & 3) * 32 + (lane & 7) * 4;
    int base = blockIdx.x * NPIX;

    // stage Q / Q^T / lam into smem (padded layout)
    for (int p = tid; p < NPIX; p += NTHR) {
        int r = p >> 7, c = p & 127;
        sQ[r * SPAD + c]  = g_Q[p];
        sQt[r * SPAD + c] = g_Qt[p];
    }
    if (tid < 128) sLam[tid] = g_lam[tid];

    // init ADMM state for this image
    for (int p = tid; p < NPIX; p += NTHR) {
        int i = p >> 7, j = p & 127;
        int idx = base + p;
        float y = Y[idx];
        g_X[idx] = y;
        g_G1[idx] = 0.f; g_G21[idx] = 0.f; g_G22[idx] = 0.f;
        g_DhZ[idx] = y - Y[base + (i << 7) + ((j - 1) & 127)];
        g_DvZ[idx] = y - Y[base + (((i - 1) & 127) << 7) + j];
    }
    __syncthreads();

    double m1d = 0.1, m2d = 0.1;
    for (int t = 0; t < 20; t++) {
        float mu1 = (float)m1d, mu2 = (float)m2d;
        float inv2 = 1.f / mu2, thr = LAM_C * inv2;

        // ---- pre: shrink + build RHS directly into smem (4 px per step) ----
        // R = mu1*X + G1 + DhT(mu2*Uh+G21) + DvT(mu2*Uv+G22)
        for (int ch = tid; ch < NPIX / 4; ch += NTHR) {
            int i = ch >> 5, c0 = (ch & 31) * 4;
            int idx = base + (i << 7) + c0;

            float4 dh = ld4(&g_DhZ[idx]), dv = ld4(&g_DvZ[idx]);
            float4 g21 = ld4(&g_G21[idx]), g22 = ld4(&g_G22[idx]);
            float4 x4 = ld4(&g_X[idx]),  g1 = ld4(&g_G1[idx]);

            float4 Ph, Pv;
            Ph.x = mu2 * shrinkf(dh.x - g21.x * inv2, thr) + g21.x;
            Ph.y = mu2 * shrinkf(dh.y - g21.y * inv2, thr) + g21.y;
            Ph.z = mu2 * shrinkf(dh.z - g21.z * inv2, thr) + g21.z;
            Ph.w = mu2 * shrinkf(dh.w - g21.w * inv2, thr) + g21.w;
            Pv.x = mu2 * shrinkf(dv.x - g22.x * inv2, thr) + g22.x;
            Pv.y = mu2 * shrinkf(dv.y - g22.y * inv2, thr) + g22.y;
            Pv.z = mu2 * shrinkf(dv.z - g22.z * inv2, thr) + g22.z;
            Pv.w = mu2 * shrinkf(dv.w - g22.w * inv2, thr) + g22.w;

            int jr = (c0 + 4) & 127;
            int idr = base + (i << 7) + jr;
            float dh_r = g_DhZ[idr], g21_r = g_G21[idr];
            float Ph4 = mu2 * shrinkf(dh_r - g21_r * inv2, thr) + g21_r;

            int idd = base + (((i + 1) & 127) << 7) + c0;
            float4 dv_d = ld4(&g_DvZ[idd]), g22_d = ld4(&g_G22[idd]);
            float4 Pvd;
            Pvd.x = mu2 * shrinkf(dv_d.x - g22_d.x * inv2, thr) + g22_d.x;
            Pvd.y = mu2 * shrinkf(dv_d.y - g22_d.y * inv2, thr) + g22_d.y;
            Pvd.z = mu2 * shrinkf(dv_d.z - g22_d.z * inv2, thr) + g22_d.z;
            Pvd.w = mu2 * shrinkf(dv_d.w - g22_d.w * inv2, thr) + g22_d.w;

            float4 R;
            R.x = mu1 * x4.x + g1.x + (Ph.x - Ph.y) + (Pv.x - Pvd.x);
            R.y = mu1 * x4.y + g1.y + (Ph.y - Ph.z) + (Pv.y - Pvd.y);
            R.z = mu1 * x4.z + g1.z + (Ph.z - Ph.w) + (Pv.z - Pvd.z);
            R.w = mu1 * x4.w + g1.w + (Ph.w - Ph4)  + (Pv.w - Pvd.w);
            st4(&sT[i * SPAD + c0], R);
        }
        __syncthreads();

        // ---- spectral solve: Z = Q^T [ (Q R Q^T) ⊙ D ] Q, all in-place in sT ----
        gemm_stage<false>(sQ,  sT,  sT, sLam, mu1, mu2, row0, col0);   // T = Q * R
        gemm_stage<true >(sT,  sQt, sT, sLam, mu1, mu2, row0, col0);   // T = (T * Q^T) ⊙ D
        gemm_stage<false>(sQt, sT,  sT, sLam, mu1, mu2, row0, col0);   // T = Q^T * T
        gemm_stage<false>(sT,  sQ,  sT, sLam, mu1, mu2, row0, col0);   // T = T * Q  (= Z)

        if (t == 19) {
            for (int ch = tid; ch < NPIX / 4; ch += NTHR) {
                int i = ch >> 5, c0 = (ch & 31) * 4;
                st4(&out[base + (i << 7) + c0], ld4(&sT[i * SPAD + c0]));
            }
        } else {
            // ---- post: gradients of Z (smem) + X/G updates; Uh/Uv recomputed ----
            for (int ch = tid; ch < NPIX / 4; ch += NTHR) {
                int i = ch >> 5, c0 = (ch & 31) * 4;
                int idx = base + (i << 7) + c0;

                float4 z = ld4(&sT[i * SPAD + c0]);
                float zl = sT[i * SPAD + ((c0 - 1) & 127)];
                float4 zu = ld4(&sT[((i - 1) & 127) * SPAD + c0]);
                float4 dh, dv;
                dh.x = z.x - zl;  dh.y = z.y - z.x;  dh.z = z.z - z.y;  dh.w = z.w - z.z;
                dv.x = z.x - zu.x; dv.y = z.y - zu.y; dv.z = z.z - zu.z; dv.w = z.w - zu.w;

                float4 dho = ld4(&g_DhZ[idx]), dvo = ld4(&g_DvZ[idx]);
                float4 g21 = ld4(&g_G21[idx]), g22 = ld4(&g_G22[idx]);
                float4 g1 = ld4(&g_G1[idx]);
                float4 w4 = ld4(&inW[idx]), y = ld4(&Y[idx]);

                // recompute Uh/Uv from pre-iteration state (bit-identical to pre's values)
                float4 uh, uv;
                uh.x = shrinkf(dho.x - g21.x * inv2, thr); uh.y = shrinkf(dho.y - g21.y * inv2, thr);
                uh.z = shrinkf(dho.z - g21.z * inv2, thr); uh.w = shrinkf(dho.w - g21.w * inv2, thr);
                uv.x = shrinkf(dvo.x - g22.x * inv2, thr); uv.y = shrinkf(dvo.y - g22.y * inv2, thr);
                uv.z = shrinkf(dvo.z - g22.z * inv2, thr); uv.w = shrinkf(dvo.w - g22.w * inv2, thr);

                float4 x, g1n, g21n, g22n;
                x.x = (w4.x * y.x + mu1 * z.x - g1.x) / (w4.x + mu1);
                x.y = (w4.y * y.y + mu1 * z.y - g1.y) / (w4.y + mu1);
                x.z = (w4.z * y.z + mu1 * z.z - g1.z) / (w4.z + mu1);
                x.w = (w4.w * y.w + mu1 * z.w - g1.w) / (w4.w + mu1);
                g1n.x = g1.x + mu1 * (x.x - z.x); g1n.y = g1.y + mu1 * (x.y - z.y);
                g1n.z = g1.z + mu1 * (x.z - z.z); g1n.w = g1.w + mu1 * (x.w - z.w);
                g21n.x = g21.x + mu2 * (uh.x - dh.x); g21n.y = g21.y + mu2 * (uh.y - dh.y);
                g21n.z = g21.z + mu2 * (uh.z - dh.z); g21n.w = g21.w + mu2 * (uh.w - dh.w);
                g22n.x = g22.x + mu2 * (uv.x - dv.x); g22n.y = g22.y + mu2 * (uv.y - dv.y);
                g22n.z = g22.z + mu2 * (uv.z - dv.z); g22n.w = g22.w + mu2 * (uv.w - dv.w);

                st4(&g_DhZ[idx], dh); st4(&g_DvZ[idx], dv);
                st4(&g_X[idx], x);    st4(&g_G1[idx], g1n);
                st4(&g_G21[idx], g21n); st4(&g_G22[idx], g22n);
            }
            __syncthreads();
        }
        m1d *= 1.05; m2d *= 1.05;
    }
}

// ======================= launcher =======================
extern "C" void kernel_launch(void* const* d_in, const int* in_sizes, int n_in,
                              void* d_out, int out_size) {
    const float* Y   = (const float*)d_in[0];
    const float* inW = (const float*)d_in[1];
    float* out = (float*)d_out;

    const int smem_bytes = (3 * 128 * SPAD + 128) * (int)sizeof(float);  // 203,264 B
    cudaFuncSetAttribute(hwtv_fused, cudaFuncAttributeMaxDynamicSharedMemorySize, smem_bytes);

    init_q_kernel<<<128, 128>>>();
    hwtv_fused<<<NIMG, NTHR, smem_bytes>>>(Y, inW, out);
}

// round 9
// speedup vs baseline: 1.9182x; 1.0767x over previous
#include <cuda_runtime.h>
#include <math.h>

#ifndef M_PI
#define M_PI 3.14159265358979323846
#endif

#define NIMG 124
#define NSIDE 128
#define NPIX (NSIDE*NSIDE)
#define NTOT (NIMG*NPIX)
#define LAM_C 0.1f
#define SPAD 132                    // smem row stride in floats (16B-aligned rows; 132≡4 mod 32 banks)
#define NTHR 512

typedef unsigned long long ull;

// ---- persistent state (no cudaMalloc allowed) ----
__device__ float g_X[NTOT], g_G1[NTOT], g_G21[NTOT], g_G22[NTOT];
__device__ float g_DhZ[NTOT], g_DvZ[NTOT];
__device__ float g_Q[NPIX];      // real orthogonal trig eigenbasis, row-major
__device__ float g_Qt[NPIX];     // its transpose
__device__ float g_lam[NSIDE];   // eigenvalues of 1D circular Laplacian

// ======================= init: Q, Q^T, eigenvalues =======================
__global__ void init_q_kernel() {
    int r = blockIdx.x, n = threadIdx.x;
    double inv = 1.0 / 128.0;
    double s1 = sqrt(inv), s2 = sqrt(2.0 * inv);
    float v;
    if (r == 0)        v = (float)s1;
    else if (r < 64)   v = (float)(s2 * cos(2.0 * M_PI * (double)r * (double)n * inv));
    else if (r == 64)  v = (n & 1) ? (float)(-s1) : (float)s1;
    else               v = (float)(s2 * sin(2.0 * M_PI * (double)(r - 64) * (double)n * inv));
    g_Q[r * NSIDE + n]  = v;
    g_Qt[n * NSIDE + r] = v;
    if (n == 0) {
        int f = (r <= 64) ? r : (r - 64);
        g_lam[r] = (float)(2.0 - 2.0 * cos(2.0 * M_PI * (double)f * inv));
    }
}

__device__ __forceinline__ float shrinkf(float x, float t) {
    return copysignf(fmaxf(fabsf(x) - t, 0.f), x);
}

// packed fp32x2 helpers (Blackwell FFMA2)
__device__ __forceinline__ ull pack2(float x) {
    ull r; asm("mov.b64 %0, {%1, %1};" : "=l"(r) : "f"(x)); return r;
}
__device__ __forceinline__ void ffma2(ull& d, ull a, ull b) {
    asm("fma.rn.f32x2 %0, %1, %2, %0;" : "+l"(d) : "l"(a), "l"(b));
}

__device__ __forceinline__ float4 ld4(const float* p) { return *(const float4*)p; }
__device__ __forceinline__ void st4(float* p, float4 v) { *(float4*)p = v; }

// ============ one 128x128x128 GEMM stage in shared memory; C may alias L or R ============
// C[m][n] = sum_k L[m][k] * R[k][n]   (optionally * spectral filter)
// 512 threads = 16 warps in a 4x4 grid of 32x32 warp tiles.
// Lane micro-tile: rows rbase + 8*i (i<4), cols col0..col0+7.
//   rbase = (w>>2)*32 + (lane>>2)    -> 8 row addrs 1 apart => banks {0,4,...,28}, 4-way bcast, clean
//   col0  = (w&3)*32 + (lane&3)*8    -> b reads: two 16B segs, 8-way bcast, clean
template<bool FILT>
__device__ __forceinline__ void gemm_stage(const float* __restrict__ Lb,
                                           const float* __restrict__ Rb,
                                           float* __restrict__ Cb,
                                           const float* __restrict__ lam,
                                           float mu1, float mu2, int rbase, int col0) {
    ull acc[4][4];
#pragma unroll
    for (int i = 0; i < 4; i++)
#pragma unroll
        for (int j = 0; j < 4; j++) acc[i][j] = 0ull;

    const float* lp = Lb + rbase * SPAD;
    const float* rp = Rb + col0;

    float4 Ac[4], An[4];
    ulonglong2 bc0, bc1, bn0, bn1;

    // prologue: A of quad 0, b of k=0
#pragma unroll
    for (int i = 0; i < 4; i++) Ac[i] = ld4(lp + (8 * i) * SPAD);
    bc0 = *(const ulonglong2*)(rp);
    bc1 = *(const ulonglong2*)(rp + 4);

#pragma unroll 4
    for (int q = 0; q < 31; q++) {            // quads 0..30: all prefetches in-range
        int k0 = q * 4;
#pragma unroll
        for (int i = 0; i < 4; i++) An[i] = ld4(lp + (8 * i) * SPAD + k0 + 4);
#pragma unroll
        for (int kk = 0; kk < 4; kk++) {
            int kn = k0 + kk + 1;             // <= 124+... <= 125..128? max q=30,kk=3 -> 124 < 128 OK
            bn0 = *(const ulonglong2*)(rp + kn * SPAD);
            bn1 = *(const ulonglong2*)(rp + kn * SPAD + 4);
#pragma unroll
            for (int i = 0; i < 4; i++) {
                float av = (kk == 0) ? Ac[i].x : (kk == 1) ? Ac[i].y : (kk == 2) ? Ac[i].z : Ac[i].w;
                ull aa = pack2(av);
                ffma2(acc[i][0], aa, bc0.x);
                ffma2(acc[i][1], aa, bc0.y);
                ffma2(acc[i][2], aa, bc1.x);
                ffma2(acc[i][3], aa, bc1.y);
            }
            bc0 = bn0; bc1 = bn1;
        }
#pragma unroll
        for (int i = 0; i < 4; i++) Ac[i] = An[i];
    }
    // last quad (k0 = 124): prefetch b only while kn < 128
#pragma unroll
    for (int kk = 0; kk < 4; kk++) {
        int kn = 124 + kk + 1;
        if (kk < 3) {
            bn0 = *(const ulonglong2*)(rp + kn * SPAD);
            bn1 = *(const ulonglong2*)(rp + kn * SPAD + 4);
        }
#pragma unroll
        for (int i = 0; i < 4; i++) {
            float av = (kk == 0) ? Ac[i].x : (kk == 1) ? Ac[i].y : (kk == 2) ? Ac[i].z : Ac[i].w;
            ull aa = pack2(av);
            ffma2(acc[i][0], aa, bc0.x);
            ffma2(acc[i][1], aa, bc0.y);
            ffma2(acc[i][2], aa, bc1.x);
            ffma2(acc[i][3], aa, bc1.y);
        }
        bc0 = bn0; bc1 = bn1;
    }
    __syncthreads();   // all reads of the (possibly aliased) buffer complete before any write

    float lc[8];
    if (FILT) {
#pragma unroll
        for (int j = 0; j < 8; j++) lc[j] = lam[col0 + j];
    }
#pragma unroll
    for (int i = 0; i < 4; i++) {
        int r = rbase + 8 * i;
        float2 v0 = *reinterpret_cast<float2*>(&acc[i][0]);
        float2 v1 = *reinterpret_cast<float2*>(&acc[i][1]);
        float2 v2 = *reinterpret_cast<float2*>(&acc[i][2]);
        float2 v3 = *reinterpret_cast<float2*>(&acc[i][3]);
        float4 va = make_float4(v0.x, v0.y, v1.x, v1.y);
        float4 vb = make_float4(v2.x, v2.y, v3.x, v3.y);
        if (FILT) {
            float lr = lam[r];
            va.x *= 1.f / (mu1 + mu2 * (lr + lc[0]));
            va.y *= 1.f / (mu1 + mu2 * (lr + lc[1]));
            va.z *= 1.f / (mu1 + mu2 * (lr + lc[2]));
            va.w *= 1.f / (mu1 + mu2 * (lr + lc[3]));
            vb.x *= 1.f / (mu1 + mu2 * (lr + lc[4]));
            vb.y *= 1.f / (mu1 + mu2 * (lr + lc[5]));
            vb.z *= 1.f / (mu1 + mu2 * (lr + lc[6]));
            vb.w *= 1.f / (mu1 + mu2 * (lr + lc[7]));
        }
        st4(&Cb[r * SPAD + col0], va);
        st4(&Cb[r * SPAD + col0 + 4], vb);
    }
    __syncthreads();   // stores visible before next stage reads
}

// ======================= fused whole-problem kernel: 1 CTA per image =======================
extern __shared__ float smem[];

__global__ void __launch_bounds__(NTHR, 1)
hwtv_fused(const float* __restrict__ Y, const float* __restrict__ inW,
           float* __restrict__ out) {
    float* sQ   = smem;
    float* sQt  = smem + 128 * SPAD;
    float* sT   = smem + 2 * 128 * SPAD;
    float* sLam = smem + 3 * 128 * SPAD;

    int tid = threadIdx.x;
    int w = tid >> 5, lane = tid & 31;
    int rbase = (w >> 2) * 32 + (lane >> 2);
    int col0  = (w & 3) * 32 + (lane & 3) * 8;
    int base = blockIdx.x * NPIX;

    // stage Q / Q^T / lam into smem (padded layout)
    for (int p = tid; p < NPIX; p += NTHR) {
        int r = p >> 7, c = p & 127;
        sQ[r * SPAD + c]  = g_Q[p];
        sQt[r * SPAD + c] = g_Qt[p];
    }
    if (tid < 128) sLam[tid] = g_lam[tid];

    // init ADMM state for this image
    for (int p = tid; p < NPIX; p += NTHR) {
        int i = p >> 7, j = p & 127;
        int idx = base + p;
        float y = Y[idx];
        g_X[idx] = y;
        g_G1[idx] = 0.f; g_G21[idx] = 0.f; g_G22[idx] = 0.f;
        g_DhZ[idx] = y - Y[base + (i << 7) + ((j - 1) & 127)];
        g_DvZ[idx] = y - Y[base + (((i - 1) & 127) << 7) + j];
    }
    __syncthreads();

    double m1d = 0.1, m2d = 0.1;
    for (int t = 0; t < 20; t++) {
        float mu1 = (float)m1d, mu2 = (float)m2d;
        float inv2 = 1.f / mu2, thr = LAM_C * inv2;

        // ---- pre: shrink + build RHS directly into smem (4 px per step) ----
        // R = mu1*X + G1 + DhT(mu2*Uh+G21) + DvT(mu2*Uv+G22)
        for (int ch = tid; ch < NPIX / 4; ch += NTHR) {
            int i = ch >> 5, c0 = (ch & 31) * 4;
            int idx = base + (i << 7) + c0;

            float4 dh = ld4(&g_DhZ[idx]), dv = ld4(&g_DvZ[idx]);
            float4 g21 = ld4(&g_G21[idx]), g22 = ld4(&g_G22[idx]);
            float4 x4 = ld4(&g_X[idx]),  g1 = ld4(&g_G1[idx]);

            float4 Ph, Pv;
            Ph.x = mu2 * shrinkf(dh.x - g21.x * inv2, thr) + g21.x;
            Ph.y = mu2 * shrinkf(dh.y - g21.y * inv2, thr) + g21.y;
            Ph.z = mu2 * shrinkf(dh.z - g21.z * inv2, thr) + g21.z;
            Ph.w = mu2 * shrinkf(dh.w - g21.w * inv2, thr) + g21.w;
            Pv.x = mu2 * shrinkf(dv.x - g22.x * inv2, thr) + g22.x;
            Pv.y = mu2 * shrinkf(dv.y - g22.y * inv2, thr) + g22.y;
            Pv.z = mu2 * shrinkf(dv.z - g22.z * inv2, thr) + g22.z;
            Pv.w = mu2 * shrinkf(dv.w - g22.w * inv2, thr) + g22.w;

            int jr = (c0 + 4) & 127;
            int idr = base + (i << 7) + jr;
            float dh_r = g_DhZ[idr], g21_r = g_G21[idr];
            float Ph4 = mu2 * shrinkf(dh_r - g21_r * inv2, thr) + g21_r;

            int idd = base + (((i + 1) & 127) << 7) + c0;
            float4 dv_d = ld4(&g_DvZ[idd]), g22_d = ld4(&g_G22[idd]);
            float4 Pvd;
            Pvd.x = mu2 * shrinkf(dv_d.x - g22_d.x * inv2, thr) + g22_d.x;
            Pvd.y = mu2 * shrinkf(dv_d.y - g22_d.y * inv2, thr) + g22_d.y;
            Pvd.z = mu2 * shrinkf(dv_d.z - g22_d.z * inv2, thr) + g22_d.z;
            Pvd.w = mu2 * shrinkf(dv_d.w - g22_d.w * inv2, thr) + g22_d.w;

            float4 R;
            R.x = mu1 * x4.x + g1.x + (Ph.x - Ph.y) + (Pv.x - Pvd.x);
            R.y = mu1 * x4.y + g1.y + (Ph.y - Ph.z) + (Pv.y - Pvd.y);
            R.z = mu1 * x4.z + g1.z + (Ph.z - Ph.w) + (Pv.z - Pvd.z);
            R.w = mu1 * x4.w + g1.w + (Ph.w - Ph4)  + (Pv.w - Pvd.w);
            st4(&sT[i * SPAD + c0], R);
        }
        __syncthreads();

        // ---- spectral solve: Z = Q^T [ (Q R Q^T) ⊙ D ] Q, all in-place in sT ----
        gemm_stage<false>(sQ,  sT,  sT, sLam, mu1, mu2, rbase, col0);   // T = Q * R
        gemm_stage<true >(sT,  sQt, sT, sLam, mu1, mu2, rbase, col0);   // T = (T * Q^T) ⊙ D
        gemm_stage<false>(sQt, sT,  sT, sLam, mu1, mu2, rbase, col0);   // T = Q^T * T
        gemm_stage<false>(sT,  sQ,  sT, sLam, mu1, mu2, rbase, col0);   // T = T * Q  (= Z)

        if (t == 19) {
            for (int ch = tid; ch < NPIX / 4; ch += NTHR) {
                int i = ch >> 5, c0 = (ch & 31) * 4;
                st4(&out[base + (i << 7) + c0], ld4(&sT[i * SPAD + c0]));
            }
        } else {
            // ---- post: gradients of Z (smem) + X/G updates; Uh/Uv recomputed ----
            for (int ch = tid; ch < NPIX / 4; ch += NTHR) {
                int i = ch >> 5, c0 = (ch & 31) * 4;
                int idx = base + (i << 7) + c0;

                float4 z = ld4(&sT[i * SPAD + c0]);
                float zl = sT[i * SPAD + ((c0 - 1) & 127)];
                float4 zu = ld4(&sT[((i - 1) & 127) * SPAD + c0]);
                float4 dh, dv;
                dh.x = z.x - zl;  dh.y = z.y - z.x;  dh.z = z.z - z.y;  dh.w = z.w - z.z;
                dv.x = z.x - zu.x; dv.y = z.y - zu.y; dv.z = z.z - zu.z; dv.w = z.w - zu.w;

                float4 dho = ld4(&g_DhZ[idx]), dvo = ld4(&g_DvZ[idx]);
                float4 g21 = ld4(&g_G21[idx]), g22 = ld4(&g_G22[idx]);
                float4 g1 = ld4(&g_G1[idx]);
                float4 w4 = ld4(&inW[idx]), y = ld4(&Y[idx]);

                // recompute Uh/Uv from pre-iteration state (bit-identical to pre's values)
                float4 uh, uv;
                uh.x = shrinkf(dho.x - g21.x * inv2, thr); uh.y = shrinkf(dho.y - g21.y * inv2, thr);
                uh.z = shrinkf(dho.z - g21.z * inv2, thr); uh.w = shrinkf(dho.w - g21.w * inv2, thr);
                uv.x = shrinkf(dvo.x - g22.x * inv2, thr); uv.y = shrinkf(dvo.y - g22.y * inv2, thr);
                uv.z = shrinkf(dvo.z - g22.z * inv2, thr); uv.w = shrinkf(dvo.w - g22.w * inv2, thr);

                float4 x, g1n, g21n, g22n;
                x.x = (w4.x * y.x + mu1 * z.x - g1.x) / (w4.x + mu1);
                x.y = (w4.y * y.y + mu1 * z.y - g1.y) / (w4.y + mu1);
                x.z = (w4.z * y.z + mu1 * z.z - g1.z) / (w4.z + mu1);
                x.w = (w4.w * y.w + mu1 * z.w - g1.w) / (w4.w + mu1);
                g1n.x = g1.x + mu1 * (x.x - z.x); g1n.y = g1.y + mu1 * (x.y - z.y);
                g1n.z = g1.z + mu1 * (x.z - z.z); g1n.w = g1.w + mu1 * (x.w - z.w);
                g21n.x = g21.x + mu2 * (uh.x - dh.x); g21n.y = g21.y + mu2 * (uh.y - dh.y);
                g21n.z = g21.z + mu2 * (uh.z - dh.z); g21n.w = g21.w + mu2 * (uh.w - dh.w);
                g22n.x = g22.x + mu2 * (uv.x - dv.x); g22n.y = g22.y + mu2 * (uv.y - dv.y);
                g22n.z = g22.z + mu2 * (uv.z - dv.z); g22n.w = g22.w + mu2 * (uv.w - dv.w);

                st4(&g_DhZ[idx], dh); st4(&g_DvZ[idx], dv);
                st4(&g_X[idx], x);    st4(&g_G1[idx], g1n);
                st4(&g_G21[idx], g21n); st4(&g_G22[idx], g22n);
            }
            __syncthreads();
        }
        m1d *= 1.05; m2d *= 1.05;
    }
}

// ======================= launcher =======================
extern "C" void kernel_launch(void* const* d_in, const int* in_sizes, int n_in,
                              void* d_out, int out_size) {
    const float* Y   = (const float*)d_in[0];
    const float* inW = (const float*)d_in[1];
    float* out = (float*)d_out;

    const int smem_bytes = (3 * 128 * SPAD + 128) * (int)sizeof(float);  // 203,264 B
    cudaFuncSetAttribute(hwtv_fused, cudaFuncAttributeMaxDynamicSharedMemorySize, smem_bytes);

    init_q_kernel<<<128, 128>>>();
    hwtv_fused<<<NIMG, NTHR, smem_bytes>>>(Y, inW, out);
}

// round 12
// speedup vs baseline: 3.2341x; 1.6860x over previous
#include <cuda_runtime.h>
#include <cuda_bf16.h>
#include <math.h>
#include <stdint.h>

#ifndef M_PI
#define M_PI 3.14159265358979323846
#endif

#define NIMG 124
#define NSIDE 128
#define NPIX (NSIDE*NSIDE)
#define NTOT (NIMG*NPIX)
#define LAM_C 0.1f
#define NTHR 512
#define SKB 136                 // bf16 tile row stride (halfwords); 272B rows -> ldmatrix conflict-free
#define ZPAD 132                // f32 Zbuf row stride

#define TILE_B (128*SKB*2)      // 34816 bytes per bf16 tile
#define OFF_QH   0
#define OFF_QL   (OFF_QH  + TILE_B)
#define OFF_QTH  (OFF_QL  + TILE_B)
#define OFF_QTL  (OFF_QTH + TILE_B)
#define OFF_BH   (OFF_QTL + TILE_B)
#define OFF_BL   (OFF_BH  + TILE_B)
#define OFF_LAM  (OFF_BL  + TILE_B)
#define SMEM_BYTES (OFF_LAM + 512)     // 209,408 B

// ---- persistent state (no cudaMalloc allowed) ----
__device__ float g_X[NTOT], g_G1[NTOT], g_G21[NTOT], g_G22[NTOT];
__device__ float g_DhZ[NTOT], g_DvZ[NTOT];
__device__ __nv_bfloat16 g_Qh[NPIX], g_Ql[NPIX], g_Qth[NPIX], g_Qtl[NPIX];
__device__ float g_lam[NSIDE];

// ======================= init: Q splits + eigenvalues =======================
__global__ void init_q_kernel() {
    int r = blockIdx.x, n = threadIdx.x;
    double inv = 1.0 / 128.0;
    double s1 = sqrt(inv), s2 = sqrt(2.0 * inv);
    float v;
    if (r == 0)        v = (float)s1;
    else if (r < 64)   v = (float)(s2 * cos(2.0 * M_PI * (double)r * (double)n * inv));
    else if (r == 64)  v = (n & 1) ? (float)(-s1) : (float)s1;
    else               v = (float)(s2 * sin(2.0 * M_PI * (double)(r - 64) * (double)n * inv));
    __nv_bfloat16 h = __float2bfloat16(v);
    __nv_bfloat16 l = __float2bfloat16(v - __bfloat162float(h));
    g_Qh[r * NSIDE + n]  = h;  g_Ql[r * NSIDE + n]  = l;
    g_Qth[n * NSIDE + r] = h;  g_Qtl[n * NSIDE + r] = l;
    if (n == 0) {
        int f = (r <= 64) ? r : (r - 64);
        g_lam[r] = (float)(2.0 - 2.0 * cos(2.0 * M_PI * (double)f * inv));
    }
}

__device__ __forceinline__ float shrinkf(float x, float t) {
    return copysignf(fmaxf(fabsf(x) - t, 0.f), x);
}
__device__ __forceinline__ float4 ld4(const float* p) { return *(const float4*)p; }
__device__ __forceinline__ void st4(float* p, float4 v) { *(float4*)p = v; }

__device__ __forceinline__ uint32_t smem_u32(const void* p) {
    uint32_t a;
    asm("{ .reg .u64 t; cvta.to.shared.u64 t, %1; cvt.u32.u64 %0, t; }" : "=r"(a) : "l"(p));
    return a;
}
__device__ __forceinline__ void ldm4(uint32_t* r, uint32_t addr) {
    asm volatile("ldmatrix.sync.aligned.m8n8.x4.shared.b16 {%0,%1,%2,%3}, [%4];"
        : "=r"(r[0]), "=r"(r[1]), "=r"(r[2]), "=r"(r[3]) : "r"(addr));
}
__device__ __forceinline__ void mma16816(float* d, const uint32_t* a, const uint32_t* b) {
    asm volatile("mma.sync.aligned.m16n8k16.row.col.f32.bf16.bf16.f32 "
        "{%0,%1,%2,%3}, {%4,%5,%6,%7}, {%8,%9}, {%0,%1,%2,%3};"
        : "+f"(d[0]), "+f"(d[1]), "+f"(d[2]), "+f"(d[3])
        : "r"(a[0]), "r"(a[1]), "r"(a[2]), "r"(a[3]), "r"(b[0]), "r"(b[1]));
}
// split float -> packed pair helpers
__device__ __forceinline__ void bsplit(float f, unsigned short& h, unsigned short& l) {
    __nv_bfloat16 hb = __float2bfloat16(f);
    __nv_bfloat16 lb = __float2bfloat16(f - __bfloat162float(hb));
    h = __bfloat16_as_ushort(hb); l = __bfloat16_as_ushort(lb);
}
__device__ __forceinline__ void split_pair(float f0, float f1, uint32_t& hp, uint32_t& lp) {
    unsigned short h0,h1,l0,l1;
    bsplit(f0,h0,l0); bsplit(f1,h1,l1);
    hp = (uint32_t)h0 | ((uint32_t)h1 << 16);
    lp = (uint32_t)l0 | ((uint32_t)l1 << 16);
}
// store float4 (row r, cols c..c+3) split into BH/BL tiles (row-major, stride SKB)
__device__ __forceinline__ void split_store4(char* BH, char* BL, int r, int c, float4 v) {
    uint32_t h0,h1,l0,l1;
    split_pair(v.x, v.y, h0, l0);
    split_pair(v.z, v.w, h1, l1);
    uint32_t o = (uint32_t)(r * SKB + c) * 2u;
    *(uint2*)(BH + o) = make_uint2(h0, h1);
    *(uint2*)(BL + o) = make_uint2(l0, l1);
}

// ======================= fused whole-problem kernel: 1 CTA per image =======================
extern __shared__ char smem[];

__global__ void __launch_bounds__(NTHR, 1)
hwtv_fused(const float* __restrict__ Y, const float* __restrict__ inW,
           float* __restrict__ out) {
    char* BH = smem + OFF_BH;
    char* BL = smem + OFF_BL;
    float* Zbuf = (float*)(smem + OFF_BH);       // aliases BH+BL after stage 4
    float* sLam = (float*)(smem + OFF_LAM);

    int tid = threadIdx.x;
    int w = tid >> 5, lane = tid & 31;
    int base = blockIdx.x * NPIX;
    uint32_t sb = smem_u32(smem);

    // warp tiling: 8 m-tiles x 2 n-halves
    int wm = w >> 1, wn = w & 1;
    int g = lane >> 3, r8 = lane & 7;
    // A-frag ldmatrix lane address components (row-major A)
    int arow = 16 * wm + r8 + (g & 1) * 8;
    int akof = (g >> 1) * 8;
    uint32_t aoff = (uint32_t)(arow * SKB + akof) * 2u;
    // B-frag x4 (pair of n8 tiles) lane address components ([n][k] storage)
    int bn_r = r8 + (g >> 1) * 8;     // n within 16-wide pair
    int bkof = (g & 1) * 8;
    // D element coords
    int drow = 16 * wm + (lane >> 2);
    int dcol0 = 64 * wn + 2 * (lane & 3);

    // stage Q/Qt bf16 splits into smem tiles; lam
    for (int p = tid; p < NPIX; p += NTHR) {
        int r = p >> 7, c = p & 127;
        uint32_t o = (uint32_t)(r * SKB + c) * 2u;
        *(unsigned short*)(smem + OFF_QH  + o) = __bfloat16_as_ushort(g_Qh[p]);
        *(unsigned short*)(smem + OFF_QL  + o) = __bfloat16_as_ushort(g_Ql[p]);
        *(unsigned short*)(smem + OFF_QTH + o) = __bfloat16_as_ushort(g_Qth[p]);
        *(unsigned short*)(smem + OFF_QTL + o) = __bfloat16_as_ushort(g_Qtl[p]);
    }
    if (tid < 128) sLam[tid] = g_lam[tid];

    // init ADMM state
    for (int p = tid; p < NPIX; p += NTHR) {
        int i = p >> 7, j = p & 127;
        int idx = base + p;
        float y = Y[idx];
        g_X[idx] = y;
        g_G1[idx] = 0.f; g_G21[idx] = 0.f; g_G22[idx] = 0.f;
        g_DhZ[idx] = y - Y[base + (i << 7) + ((j - 1) & 127)];
        g_DvZ[idx] = y - Y[base + (((i - 1) & 127) << 7) + j];
    }
    __syncthreads();

    double m1d = 0.1, m2d = 0.1;
    for (int t = 0; t < 20; t++) {
        float mu1 = (float)m1d, mu2 = (float)m2d;
        float inv2 = 1.f / mu2, thr = LAM_C * inv2;

        // ---- pre: shrink + RHS -> split into BH/BL (row-major [n][k]) ----
        for (int ch = tid; ch < NPIX / 4; ch += NTHR) {
            int i = ch >> 5, c0 = (ch & 31) * 4;
            int idx = base + (i << 7) + c0;

            float4 dh = ld4(&g_DhZ[idx]), dv = ld4(&g_DvZ[idx]);
            float4 g21 = ld4(&g_G21[idx]), g22 = ld4(&g_G22[idx]);
            float4 x4 = ld4(&g_X[idx]),  g1 = ld4(&g_G1[idx]);

            float4 Ph, Pv;
            Ph.x = mu2 * shrinkf(dh.x - g21.x * inv2, thr) + g21.x;
            Ph.y = mu2 * shrinkf(dh.y - g21.y * inv2, thr) + g21.y;
            Ph.z = mu2 * shrinkf(dh.z - g21.z * inv2, thr) + g21.z;
            Ph.w = mu2 * shrinkf(dh.w - g21.w * inv2, thr) + g21.w;
            Pv.x = mu2 * shrinkf(dv.x - g22.x * inv2, thr) + g22.x;
            Pv.y = mu2 * shrinkf(dv.y - g22.y * inv2, thr) + g22.y;
            Pv.z = mu2 * shrinkf(dv.z - g22.z * inv2, thr) + g22.z;
            Pv.w = mu2 * shrinkf(dv.w - g22.w * inv2, thr) + g22.w;

            int idr = base + (i << 7) + ((c0 + 4) & 127);
            float dh_r = g_DhZ[idr], g21_r = g_G21[idr];
            float Ph4 = mu2 * shrinkf(dh_r - g21_r * inv2, thr) + g21_r;

            int idd = base + (((i + 1) & 127) << 7) + c0;
            float4 dv_d = ld4(&g_DvZ[idd]), g22_d = ld4(&g_G22[idd]);
            float4 Pvd;
            Pvd.x = mu2 * shrinkf(dv_d.x - g22_d.x * inv2, thr) + g22_d.x;
            Pvd.y = mu2 * shrinkf(dv_d.y - g22_d.y * inv2, thr) + g22_d.y;
            Pvd.z = mu2 * shrinkf(dv_d.z - g22_d.z * inv2, thr) + g22_d.z;
            Pvd.w = mu2 * shrinkf(dv_d.w - g22_d.w * inv2, thr) + g22_d.w;

            float4 R;
            R.x = mu1 * x4.x + g1.x + (Ph.x - Ph.y) + (Pv.x - Pvd.x);
            R.y = mu1 * x4.y + g1.y + (Ph.y - Ph.z) + (Pv.y - Pvd.y);
            R.z = mu1 * x4.z + g1.z + (Ph.z - Ph.w) + (Pv.z - Pvd.z);
            R.w = mu1 * x4.w + g1.w + (Ph.w - Ph4)  + (Pv.w - Pvd.w);
            split_store4(BH, BL, i, c0, R);
        }
        __syncthreads();

        // ---- 4 tensor stages: C = A · B^T, A in {Q, Qt}, B = previous C ----
#pragma unroll 1
        for (int st = 0; st < 4; st++) {
            uint32_t aH = sb + ((st < 2) ? OFF_QH : OFF_QTH) + aoff;
            uint32_t aL = sb + ((st < 2) ? OFF_QL : OFF_QTL) + aoff;

            float d[8][4];
#pragma unroll
            for (int j = 0; j < 8; j++)
#pragma unroll
                for (int e = 0; e < 4; e++) d[j][e] = 0.f;

#pragma unroll 1
            for (int ks = 0; ks < 8; ks++) {
                uint32_t k2 = (uint32_t)(ks * 16) * 2u;
                uint32_t Ah[4], Al[4], Bh[16], Bl[16];
                ldm4(Ah, aH + k2);
                ldm4(Al, aL + k2);
#pragma unroll
                for (int p = 0; p < 4; p++) {
                    int n = 64 * wn + 16 * p + bn_r;
                    uint32_t bo = (uint32_t)(n * SKB + bkof) * 2u + k2;
                    ldm4(Bh + 4 * p, sb + OFF_BH + bo);
                    ldm4(Bl + 4 * p, sb + OFF_BL + bo);
                }
#pragma unroll
                for (int j = 0; j < 8; j++) {
                    const uint32_t* bh = Bh + 4 * (j >> 1) + 2 * (j & 1);
                    const uint32_t* bl = Bl + 4 * (j >> 1) + 2 * (j & 1);
                    mma16816(d[j], Ah, bh);
                    mma16816(d[j], Ah, bl);
                    mma16816(d[j], Al, bh);
                }
            }
            __syncthreads();   // all reads of BH/BL done before overwrite

            if (st < 3) {
                bool filt = (st == 1);
                float lr0 = filt ? sLam[drow] : 0.f;
                float lr1 = filt ? sLam[drow + 8] : 0.f;
#pragma unroll
                for (int j = 0; j < 8; j++) {
                    int c = dcol0 + 8 * j;
                    float f0 = d[j][0], f1 = d[j][1], f2 = d[j][2], f3 = d[j][3];
                    if (filt) {
                        float la = sLam[c], lb = sLam[c + 1];
                        f0 *= 1.f / (mu1 + mu2 * (lr0 + la));
                        f1 *= 1.f / (mu1 + mu2 * (lr0 + lb));
                        f2 *= 1.f / (mu1 + mu2 * (lr1 + la));
                        f3 *= 1.f / (mu1 + mu2 * (lr1 + lb));
                    }
                    uint32_t hp, lp;
                    uint32_t o0 = (uint32_t)(drow * SKB + c) * 2u;
                    uint32_t o1 = (uint32_t)((drow + 8) * SKB + c) * 2u;
                    split_pair(f0, f1, hp, lp);
                    *(uint32_t*)(BH + o0) = hp; *(uint32_t*)(BL + o0) = lp;
                    split_pair(f2, f3, hp, lp);
                    *(uint32_t*)(BH + o1) = hp; *(uint32_t*)(BL + o1) = lp;
                }
            } else if (t == 19) {
                float* ob = out + base;
#pragma unroll
                for (int j = 0; j < 8; j++) {
                    int c = dcol0 + 8 * j;
                    *(float2*)(ob + drow * 128 + c)       = make_float2(d[j][0], d[j][1]);
                    *(float2*)(ob + (drow + 8) * 128 + c) = make_float2(d[j][2], d[j][3]);
                }
            } else {
#pragma unroll
                for (int j = 0; j < 8; j++) {
                    int c = dcol0 + 8 * j;
                    *(float2*)(Zbuf + drow * ZPAD + c)       = make_float2(d[j][0], d[j][1]);
                    *(float2*)(Zbuf + (drow + 8) * ZPAD + c) = make_float2(d[j][2], d[j][3]);
                }
            }
            __syncthreads();
        }

        if (t < 19) {
            // ---- post: gradients of Z (Zbuf) + X/G updates ----
            for (int ch = tid; ch < NPIX / 4; ch += NTHR) {
                int i = ch >> 5, c0 = (ch & 31) * 4;
                int idx = base + (i << 7) + c0;

                float4 z = ld4(&Zbuf[i * ZPAD + c0]);
                float zl = Zbuf[i * ZPAD + ((c0 - 1) & 127)];
                float4 zu = ld4(&Zbuf[((i - 1) & 127) * ZPAD + c0]);
                float4 dh, dv;
                dh.x = z.x - zl;  dh.y = z.y - z.x;  dh.z = z.z - z.y;  dh.w = z.w - z.z;
                dv.x = z.x - zu.x; dv.y = z.y - zu.y; dv.z = z.z - zu.z; dv.w = z.w - zu.w;

                float4 dho = ld4(&g_DhZ[idx]), dvo = ld4(&g_DvZ[idx]);
                float4 g21 = ld4(&g_G21[idx]), g22 = ld4(&g_G22[idx]);
                float4 g1 = ld4(&g_G1[idx]);
                float4 w4 = ld4(&inW[idx]), y = ld4(&Y[idx]);

                float4 uh, uv;
                uh.x = shrinkf(dho.x - g21.x * inv2, thr); uh.y = shrinkf(dho.y - g21.y * inv2, thr);
                uh.z = shrinkf(dho.z - g21.z * inv2, thr); uh.w = shrinkf(dho.w - g21.w * inv2, thr);
                uv.x = shrinkf(dvo.x - g22.x * inv2, thr); uv.y = shrinkf(dvo.y - g22.y * inv2, thr);
                uv.z = shrinkf(dvo.z - g22.z * inv2, thr); uv.w = shrinkf(dvo.w - g22.w * inv2, thr);

                float4 x, g1n, g21n, g22n;
                x.x = (w4.x * y.x + mu1 * z.x - g1.x) / (w4.x + mu1);
                x.y = (w4.y * y.y + mu1 * z.y - g1.y) / (w4.y + mu1);
                x.z = (w4.z * y.z + mu1 * z.z - g1.z) / (w4.z + mu1);
                x.w = (w4.w * y.w + mu1 * z.w - g1.w) / (w4.w + mu1);
                g1n.x = g1.x + mu1 * (x.x - z.x); g1n.y = g1.y + mu1 * (x.y - z.y);
                g1n.z = g1.z + mu1 * (x.z - z.z); g1n.w = g1.w + mu1 * (x.w - z.w);
                g21n.x = g21.x + mu2 * (uh.x - dh.x); g21n.y = g21.y + mu2 * (uh.y - dh.y);
                g21n.z = g21.z + mu2 * (uh.z - dh.z); g21n.w = g21.w + mu2 * (uh.w - dh.w);
                g22n.x = g22.x + mu2 * (uv.x - dv.x); g22n.y = g22.y + mu2 * (uv.y - dv.y);
                g22n.z = g22.z + mu2 * (uv.z - dv.z); g22n.w = g22.w + mu2 * (uv.w - dv.w);

                st4(&g_DhZ[idx], dh); st4(&g_DvZ[idx], dv);
                st4(&g_X[idx], x);    st4(&g_G1[idx], g1n);
                st4(&g_G21[idx], g21n); st4(&g_G22[idx], g22n);
            }
            __syncthreads();
        }
        m1d *= 1.05; m2d *= 1.05;
    }
}

// ======================= launcher =======================
extern "C" void kernel_launch(void* const* d_in, const int* in_sizes, int n_in,
                              void* d_out, int out_size) {
    const float* Y   = (const float*)d_in[0];
    const float* inW = (const float*)d_in[1];
    float* out = (float*)d_out;

    cudaFuncSetAttribute(hwtv_fused, cudaFuncAttributeMaxDynamicSharedMemorySize, SMEM_BYTES);

    init_q_kernel<<<128, 128>>>();
    hwtv_fused<<<NIMG, NTHR, SMEM_BYTES>>>(Y, inW, out);
}

// round 14
// speedup vs baseline: 3.3216x; 1.0270x over previous
#include <cuda_runtime.h>
#include <cuda_bf16.h>
#include <math.h>
#include <stdint.h>

#ifndef M_PI
#define M_PI 3.14159265358979323846
#endif

#define NIMG 124
#define NSIDE 128
#define NPIX (NSIDE*NSIDE)
#define NTOT (NIMG*NPIX)
#define LAM_C 0.1f
#define NTHR 512
#define SKB 136                 // bf16 tile row stride (halfwords); 272B rows -> ldmatrix conflict-free
#define ZPAD 132                // f32 Zbuf row stride

#define TILE_B (128*SKB*2)      // 34816 bytes per bf16 tile
#define OFF_QH   0
#define OFF_QL   (OFF_QH  + TILE_B)
#define OFF_QTH  (OFF_QL  + TILE_B)
#define OFF_QTL  (OFF_QTH + TILE_B)
#define OFF_BH   (OFF_QTL + TILE_B)
#define OFF_BL   (OFF_BH  + TILE_B)
#define OFF_LAM  (OFF_BL  + TILE_B)
#define SMEM_BYTES (OFF_LAM + 512)     // 209,408 B

// ---- persistent state (no cudaMalloc allowed) ----
__device__ float g_X[NTOT], g_G1[NTOT], g_G21[NTOT], g_G22[NTOT];
__device__ float g_DhZ[NTOT], g_DvZ[NTOT];
__device__ __nv_bfloat16 g_Qh[NPIX], g_Ql[NPIX], g_Qth[NPIX], g_Qtl[NPIX];
__device__ float g_lam[NSIDE];

// ======================= init: Q splits + eigenvalues =======================
__global__ void init_q_kernel() {
    int r = blockIdx.x, n = threadIdx.x;
    double inv = 1.0 / 128.0;
    double s1 = sqrt(inv), s2 = sqrt(2.0 * inv);
    float v;
    if (r == 0)        v = (float)s1;
    else if (r < 64)   v = (float)(s2 * cos(2.0 * M_PI * (double)r * (double)n * inv));
    else if (r == 64)  v = (n & 1) ? (float)(-s1) : (float)s1;
    else               v = (float)(s2 * sin(2.0 * M_PI * (double)(r - 64) * (double)n * inv));
    __nv_bfloat16 h = __float2bfloat16(v);
    __nv_bfloat16 l = __float2bfloat16(v - __bfloat162float(h));
    g_Qh[r * NSIDE + n]  = h;  g_Ql[r * NSIDE + n]  = l;
    g_Qth[n * NSIDE + r] = h;  g_Qtl[n * NSIDE + r] = l;
    if (n == 0) {
        int f = (r <= 64) ? r : (r - 64);
        g_lam[r] = (float)(2.0 - 2.0 * cos(2.0 * M_PI * (double)f * inv));
    }
}

__device__ __forceinline__ float shrinkf(float x, float t) {
    return copysignf(fmaxf(fabsf(x) - t, 0.f), x);
}
__device__ __forceinline__ float4 ld4(const float* p) { return *(const float4*)p; }
__device__ __forceinline__ void st4(float* p, float4 v) { *(float4*)p = v; }

__device__ __forceinline__ uint32_t smem_u32(const void* p) {
    uint32_t a;
    asm("{ .reg .u64 t; cvta.to.shared.u64 t, %1; cvt.u32.u64 %0, t; }" : "=r"(a) : "l"(p));
    return a;
}
__device__ __forceinline__ void ldm4(uint32_t* r, uint32_t addr) {
    asm volatile("ldmatrix.sync.aligned.m8n8.x4.shared.b16 {%0,%1,%2,%3}, [%4];"
        : "=r"(r[0]), "=r"(r[1]), "=r"(r[2]), "=r"(r[3]) : "r"(addr));
}
__device__ __forceinline__ void mma16816(float* d, const uint32_t* a, const uint32_t* b) {
    asm volatile("mma.sync.aligned.m16n8k16.row.col.f32.bf16.bf16.f32 "
        "{%0,%1,%2,%3}, {%4,%5,%6,%7}, {%8,%9}, {%0,%1,%2,%3};"
        : "+f"(d[0]), "+f"(d[1]), "+f"(d[2]), "+f"(d[3])
        : "r"(a[0]), "r"(a[1]), "r"(a[2]), "r"(a[3]), "r"(b[0]), "r"(b[1]));
}
// split float -> packed pair helpers
__device__ __forceinline__ void bsplit(float f, unsigned short& h, unsigned short& l) {
    __nv_bfloat16 hb = __float2bfloat16(f);
    __nv_bfloat16 lb = __float2bfloat16(f - __bfloat162float(hb));
    h = __bfloat16_as_ushort(hb); l = __bfloat16_as_ushort(lb);
}
__device__ __forceinline__ void split_pair(float f0, float f1, uint32_t& hp, uint32_t& lp) {
    unsigned short h0,h1,l0,l1;
    bsplit(f0,h0,l0); bsplit(f1,h1,l1);
    hp = (uint32_t)h0 | ((uint32_t)h1 << 16);
    lp = (uint32_t)l0 | ((uint32_t)l1 << 16);
}
// store float4 (row r, cols c..c+3) split into BH/BL tiles (row-major, stride SKB)
__device__ __forceinline__ void split_store4(char* BH, char* BL, int r, int c, float4 v) {
    uint32_t h0,h1,l0,l1;
    split_pair(v.x, v.y, h0, l0);
    split_pair(v.z, v.w, h1, l1);
    uint32_t o = (uint32_t)(r * SKB + c) * 2u;
    *(uint2*)(BH + o) = make_uint2(h0, h1);
    *(uint2*)(BL + o) = make_uint2(l0, l1);
}

// ---- fragment bundle for one k16-step of an m32 x n32 warp tile ----
struct Frag { uint32_t Ah[8], Al[8], Bh[8], Bl[8]; };

__device__ __forceinline__ void load_frag(Frag& F, uint32_t aH, uint32_t aL,
                                          uint32_t bH, uint32_t bL, uint32_t k2) {
    const uint32_t T16 = (uint32_t)(16 * SKB * 2);
    ldm4(F.Ah,     aH + k2);
    ldm4(F.Ah + 4, aH + T16 + k2);
    ldm4(F.Al,     aL + k2);
    ldm4(F.Al + 4, aL + T16 + k2);
    ldm4(F.Bh,     bH + k2);
    ldm4(F.Bh + 4, bH + T16 + k2);
    ldm4(F.Bl,     bL + k2);
    ldm4(F.Bl + 4, bL + T16 + k2);
}

__device__ __forceinline__ void comp_frag(float d[2][4][4], const Frag& F) {
#pragma unroll
    for (int mi = 0; mi < 2; mi++) {
        const uint32_t* Ah = F.Ah + 4 * mi;
        const uint32_t* Al = F.Al + 4 * mi;
#pragma unroll
        for (int j = 0; j < 4; j++) {
            const uint32_t* bh = F.Bh + ((j >> 1) << 2) + ((j & 1) << 1);
            const uint32_t* bl = F.Bl + ((j >> 1) << 2) + ((j & 1) << 1);
            mma16816(d[mi][j], Ah, bh);
            mma16816(d[mi][j], Ah, bl);
            mma16816(d[mi][j], Al, bh);
        }
    }
}

// ======================= fused whole-problem kernel: 1 CTA per image =======================
extern __shared__ char smem[];

__global__ void __launch_bounds__(NTHR, 1)
hwtv_fused(const float* __restrict__ Y, const float* __restrict__ inW,
           float* __restrict__ out) {
    char* BH = smem + OFF_BH;
    char* BL = smem + OFF_BL;
    float* Zbuf = (float*)(smem + OFF_BH);       // aliases BH+BL after stage 4
    float* sLam = (float*)(smem + OFF_LAM);

    int tid = threadIdx.x;
    int w = tid >> 5, lane = tid & 31;
    int base = blockIdx.x * NPIX;
    uint32_t sb = smem_u32(smem);

    // warp tiling: 4x4 grid of m32 x n32 tiles
    int wm = w >> 2, wn = w & 3;
    int g = lane >> 3, r8 = lane & 7;
    uint32_t aoff = (uint32_t)((32 * wm + r8 + (g & 1) * 8) * SKB + (g >> 1) * 8) * 2u;
    uint32_t boff = (uint32_t)((32 * wn + r8 + (g >> 1) * 8) * SKB + (g & 1) * 8) * 2u;
    int drow = 32 * wm + (lane >> 2);       // +16*mi, +8 for upper half of m16 tile
    int dcol = 32 * wn + 2 * (lane & 3);    // +8*j

    // stage Q/Qt bf16 splits into smem tiles; lam
    for (int p = tid; p < NPIX; p += NTHR) {
        int r = p >> 7, c = p & 127;
        uint32_t o = (uint32_t)(r * SKB + c) * 2u;
        *(unsigned short*)(smem + OFF_QH  + o) = __bfloat16_as_ushort(g_Qh[p]);
        *(unsigned short*)(smem + OFF_QL  + o) = __bfloat16_as_ushort(g_Ql[p]);
        *(unsigned short*)(smem + OFF_QTH + o) = __bfloat16_as_ushort(g_Qth[p]);
        *(unsigned short*)(smem + OFF_QTL + o) = __bfloat16_as_ushort(g_Qtl[p]);
    }
    if (tid < 128) sLam[tid] = g_lam[tid];

    // init ADMM state
    for (int p = tid; p < NPIX; p += NTHR) {
        int i = p >> 7, j = p & 127;
        int idx = base + p;
        float y = Y[idx];
        g_X[idx] = y;
        g_G1[idx] = 0.f; g_G21[idx] = 0.f; g_G22[idx] = 0.f;
        g_DhZ[idx] = y - Y[base + (i << 7) + ((j - 1) & 127)];
        g_DvZ[idx] = y - Y[base + (((i - 1) & 127) << 7) + j];
    }
    __syncthreads();

    double m1d = 0.1, m2d = 0.1;
    for (int t = 0; t < 20; t++) {
        float mu1 = (float)m1d, mu2 = (float)m2d;
        float inv2 = 1.f / mu2, thr = LAM_C * inv2;

        // ---- pre: shrink + RHS -> split into BH/BL (row-major [n][k]) ----
        for (int ch = tid; ch < NPIX / 4; ch += NTHR) {
            int i = ch >> 5, c0 = (ch & 31) * 4;
            int idx = base + (i << 7) + c0;

            float4 dh = ld4(&g_DhZ[idx]), dv = ld4(&g_DvZ[idx]);
            float4 g21 = ld4(&g_G21[idx]), g22 = ld4(&g_G22[idx]);
            float4 x4 = ld4(&g_X[idx]),  g1 = ld4(&g_G1[idx]);

            float4 Ph, Pv;
            Ph.x = mu2 * shrinkf(dh.x - g21.x * inv2, thr) + g21.x;
            Ph.y = mu2 * shrinkf(dh.y - g21.y * inv2, thr) + g21.y;
            Ph.z = mu2 * shrinkf(dh.z - g21.z * inv2, thr) + g21.z;
            Ph.w = mu2 * shrinkf(dh.w - g21.w * inv2, thr) + g21.w;
            Pv.x = mu2 * shrinkf(dv.x - g22.x * inv2, thr) + g22.x;
            Pv.y = mu2 * shrinkf(dv.y - g22.y * inv2, thr) + g22.y;
            Pv.z = mu2 * shrinkf(dv.z - g22.z * inv2, thr) + g22.z;
            Pv.w = mu2 * shrinkf(dv.w - g22.w * inv2, thr) + g22.w;

            int idr = base + (i << 7) + ((c0 + 4) & 127);
            float dh_r = g_DhZ[idr], g21_r = g_G21[idr];
            float Ph4 = mu2 * shrinkf(dh_r - g21_r * inv2, thr) + g21_r;

            int idd = base + (((i + 1) & 127) << 7) + c0;
            float4 dv_d = ld4(&g_DvZ[idd]), g22_d = ld4(&g_G22[idd]);
            float4 Pvd;
            Pvd.x = mu2 * shrinkf(dv_d.x - g22_d.x * inv2, thr) + g22_d.x;
            Pvd.y = mu2 * shrinkf(dv_d.y - g22_d.y * inv2, thr) + g22_d.y;
            Pvd.z = mu2 * shrinkf(dv_d.z - g22_d.z * inv2, thr) + g22_d.z;
            Pvd.w = mu2 * shrinkf(dv_d.w - g22_d.w * inv2, thr) + g22_d.w;

            float4 R;
            R.x = mu1 * x4.x + g1.x + (Ph.x - Ph.y) + (Pv.x - Pvd.x);
            R.y = mu1 * x4.y + g1.y + (Ph.y - Ph.z) + (Pv.y - Pvd.y);
            R.z = mu1 * x4.z + g1.z + (Ph.z - Ph.w) + (Pv.z - Pvd.z);
            R.w = mu1 * x4.w + g1.w + (Ph.w - Ph4)  + (Pv.w - Pvd.w);
            split_store4(BH, BL, i, c0, R);
        }
        __syncthreads();

        // ---- 4 tensor stages: C = A · B^T, A in {Q, Qt}, B = previous C ----
#pragma unroll 1
        for (int st = 0; st < 4; st++) {
            uint32_t aHb = sb + ((st < 2) ? OFF_QH : OFF_QTH) + aoff;
            uint32_t aLb = sb + ((st < 2) ? OFF_QL : OFF_QTL) + aoff;
            uint32_t bHb = sb + OFF_BH + boff;
            uint32_t bLb = sb + OFF_BL + boff;

            float d[2][4][4];
#pragma unroll
            for (int mi = 0; mi < 2; mi++)
#pragma unroll
                for (int j = 0; j < 4; j++)
#pragma unroll
                    for (int e = 0; e < 4; e++) d[mi][j][e] = 0.f;

            Frag f0, f1;
            load_frag(f0, aHb, aLb, bHb, bLb, 0);
#pragma unroll
            for (int ks = 0; ks < 8; ks++) {
                if (ks < 7)
                    load_frag((ks & 1) ? f0 : f1, aHb, aLb, bHb, bLb, (uint32_t)(ks + 1) * 32u);
                comp_frag(d, (ks & 1) ? f1 : f0);
            }
            __syncthreads();   // all reads of BH/BL done before overwrite

            if (st < 3) {
                bool filt = (st == 1);
#pragma unroll
                for (int mi = 0; mi < 2; mi++) {
                    int r0 = drow + 16 * mi;
                    float lr0 = filt ? sLam[r0] : 0.f;
                    float lr1 = filt ? sLam[r0 + 8] : 0.f;
#pragma unroll
                    for (int j = 0; j < 4; j++) {
                        int c = dcol + 8 * j;
                        float f0v = d[mi][j][0], f1v = d[mi][j][1];
                        float f2v = d[mi][j][2], f3v = d[mi][j][3];
                        if (filt) {
                            float la = sLam[c], lb = sLam[c + 1];
                            f0v *= 1.f / (mu1 + mu2 * (lr0 + la));
                            f1v *= 1.f / (mu1 + mu2 * (lr0 + lb));
                            f2v *= 1.f / (mu1 + mu2 * (lr1 + la));
                            f3v *= 1.f / (mu1 + mu2 * (lr1 + lb));
                        }
                        uint32_t hp, lp;
                        uint32_t o0 = (uint32_t)(r0 * SKB + c) * 2u;
                        uint32_t o1 = (uint32_t)((r0 + 8) * SKB + c) * 2u;
                        split_pair(f0v, f1v, hp, lp);
                        *(uint32_t*)(BH + o0) = hp; *(uint32_t*)(BL + o0) = lp;
                        split_pair(f2v, f3v, hp, lp);
                        *(uint32_t*)(BH + o1) = hp; *(uint32_t*)(BL + o1) = lp;
                    }
                }
            } else if (t == 19) {
                float* ob = out + base;
#pragma unroll
                for (int mi = 0; mi < 2; mi++) {
                    int r0 = drow + 16 * mi;
#pragma unroll
                    for (int j = 0; j < 4; j++) {
                        int c = dcol + 8 * j;
                        *(float2*)(ob + r0 * 128 + c)       = make_float2(d[mi][j][0], d[mi][j][1]);
                        *(float2*)(ob + (r0 + 8) * 128 + c) = make_float2(d[mi][j][2], d[mi][j][3]);
                    }
                }
            } else {
#pragma unroll
                for (int mi = 0; mi < 2; mi++) {
                    int r0 = drow + 16 * mi;
#pragma unroll
                    for (int j = 0; j < 4; j++) {
                        int c = dcol + 8 * j;
                        *(float2*)(Zbuf + r0 * ZPAD + c)       = make_float2(d[mi][j][0], d[mi][j][1]);
                        *(float2*)(Zbuf + (r0 + 8) * ZPAD + c) = make_float2(d[mi][j][2], d[mi][j][3]);
                    }
                }
            }
            __syncthreads();
        }

        if (t < 19) {
            // ---- post: gradients of Z (Zbuf) + X/G updates ----
            for (int ch = tid; ch < NPIX / 4; ch += NTHR) {
                int i = ch >> 5, c0 = (ch & 31) * 4;
                int idx = base + (i << 7) + c0;

                float4 z = ld4(&Zbuf[i * ZPAD + c0]);
                float zl = Zbuf[i * ZPAD + ((c0 - 1) & 127)];
                float4 zu = ld4(&Zbuf[((i - 1) & 127) * ZPAD + c0]);
                float4 dh, dv;
                dh.x = z.x - zl;  dh.y = z.y - z.x;  dh.z = z.z - z.y;  dh.w = z.w - z.z;
                dv.x = z.x - zu.x; dv.y = z.y - zu.y; dv.z = z.z - zu.z; dv.w = z.w - zu.w;

                float4 dho = ld4(&g_DhZ[idx]), dvo = ld4(&g_DvZ[idx]);
                float4 g21 = ld4(&g_G21[idx]), g22 = ld4(&g_G22[idx]);
                float4 g1 = ld4(&g_G1[idx]);
                float4 w4 = ld4(&inW[idx]), y = ld4(&Y[idx]);

                float4 uh, uv;
                uh.x = shrinkf(dho.x - g21.x * inv2, thr); uh.y = shrinkf(dho.y - g21.y * inv2, thr);
                uh.z = shrinkf(dho.z - g21.z * inv2, thr); uh.w = shrinkf(dho.w - g21.w * inv2, thr);
                uv.x = shrinkf(dvo.x - g22.x * inv2, thr); uv.y = shrinkf(dvo.y - g22.y * inv2, thr);
                uv.z = shrinkf(dvo.z - g22.z * inv2, thr); uv.w = shrinkf(dvo.w - g22.w * inv2, thr);

                float4 x, g1n, g21n, g22n;
                x.x = (w4.x * y.x + mu1 * z.x - g1.x) / (w4.x + mu1);
                x.y = (w4.y * y.y + mu1 * z.y - g1.y) / (w4.y + mu1);
                x.z = (w4.z * y.z + mu1 * z.z - g1.z) / (w4.z + mu1);
                x.w = (w4.w * y.w + mu1 * z.w - g1.w) / (w4.w + mu1);
                g1n.x = g1.x + mu1 * (x.x - z.x); g1n.y = g1.y + mu1 * (x.y - z.y);
                g1n.z = g1.z + mu1 * (x.z - z.z); g1n.w = g1.w + mu1 * (x.w - z.w);
                g21n.x = g21.x + mu2 * (uh.x - dh.x); g21n.y = g21.y + mu2 * (uh.y - dh.y);
                g21n.z = g21.z + mu2 * (uh.z - dh.z); g21n.w = g21.w + mu2 * (uh.w - dh.w);
                g22n.x = g22.x + mu2 * (uv.x - dv.x); g22n.y = g22.y + mu2 * (uv.y - dv.y);
                g22n.z = g22.z + mu2 * (uv.z - dv.z); g22n.w = g22.w + mu2 * (uv.w - dv.w);

                st4(&g_DhZ[idx], dh); st4(&g_DvZ[idx], dv);
                st4(&g_X[idx], x);    st4(&g_G1[idx], g1n);
                st4(&g_G21[idx], g21n); st4(&g_G22[idx], g22n);
            }
            __syncthreads();
        }
        m1d *= 1.05; m2d *= 1.05;
    }
}

// ======================= launcher =======================
extern "C" void kernel_launch(void* const* d_in, const int* in_sizes, int n_in,
                              void* d_out, int out_size) {
    const float* Y   = (const float*)d_in[0];
    const float* inW = (const float*)d_in[1];
    float* out = (float*)d_out;

    cudaFuncSetAttribute(hwtv_fused, cudaFuncAttributeMaxDynamicSharedMemorySize, SMEM_BYTES);

    init_q_kernel<<<128, 128>>>();
    hwtv_fused<<<NIMG, NTHR, SMEM_BYTES>>>(Y, inW, out);
}